// round 8
// baseline (speedup 1.0000x reference)
#include <cuda_runtime.h>

#define N_ENT   100000
#define N_REL   16
#define DIM     64
#define N_EDGES 1600000

// ---------------- device scratch (no allocs allowed) ----------------
__device__ float g_proj[(size_t)N_REL * N_ENT * DIM];   // 409.6 MB
__device__ float g_att[N_EDGES];                        // att -> exp -> normalized w
__device__ int   g_mx[N_ENT];                           // float-ordered int keys
__device__ float g_denom[N_ENT];
__device__ float g_agg1[N_ENT * DIM];
__device__ float g_agg2[N_ENT * DIM];
__device__ float g_h1[N_ENT * DIM];                     // unnormalized layer-1 h

// monotone float <-> int key for atomicMax on floats
__device__ __forceinline__ int fkey(float f) {
    int i = __float_as_int(f);
    return (i >= 0) ? i : (i ^ 0x7FFFFFFF);
}
__device__ __forceinline__ float fdecode(int k) {
    return __int_as_float((k >= 0) ? k : (k ^ 0x7FFFFFFF));
}

// fast tanh: (e^2x - 1)/(e^2x + 1), MUFU.EX2 + MUFU.RCP, ~1e-6 rel err
__device__ __forceinline__ float ftanh(float x) {
    x = fminf(fmaxf(x, -15.f), 15.f);
    float e = __expf(2.f * x);
    return __fdividef(e - 1.f, e + 1.f);
}

// ---------------- init: zero accumulators, reset softmax state ----------------
__global__ void k_init() {
    int idx = blockIdx.x * blockDim.x + threadIdx.x;
    if (idx < N_ENT * DIM) {
        g_agg1[idx] = 0.f;
        g_agg2[idx] = 0.f;
        if (idx < N_ENT) {
            g_mx[idx] = (int)0x80000000;   // INT_MIN: below every key
            g_denom[idx] = 0.f;
        }
    }
}

// ---------------- proj[r,n,:] = ent[n,:] @ W_R[r] ----------------
// block = 256 thr, tile = 64 nodes x 64 cols for one relation.
// warp w owns rows w*8..w*8+7; lane owns cols 2*lane, 2*lane+1.
__global__ void k_proj(const float* __restrict__ ent, const float* __restrict__ WR) {
    __shared__ float Es[64][64];   // entity tile (rows broadcast-read)
    __shared__ float Ws[64][64];   // W_R[r]
    const int r  = blockIdx.y;
    const int n0 = blockIdx.x * 64;
    const int tid = threadIdx.x;

    const float* Wr = WR + (size_t)r * 64 * 64;
#pragma unroll
    for (int k = 0; k < 4; k++) {
        int idx = tid + k * 256;          // 0..1023 float4 slots
        int row = idx >> 4;
        int c4  = (idx & 15) * 4;
        *(float4*)&Ws[row][c4] = *(const float4*)&Wr[row * 64 + c4];
        int gr = n0 + row;
        float4 e4 = make_float4(0.f, 0.f, 0.f, 0.f);
        if (gr < N_ENT) e4 = *(const float4*)&ent[(size_t)gr * 64 + c4];
        *(float4*)&Es[row][c4] = e4;
    }
    __syncthreads();

    const int w = tid >> 5, lane = tid & 31;
    float acc[8][2];
#pragma unroll
    for (int i = 0; i < 8; i++) { acc[i][0] = 0.f; acc[i][1] = 0.f; }

#pragma unroll 8
    for (int d = 0; d < 64; d++) {
        float2 w2 = *(const float2*)&Ws[d][lane * 2];
#pragma unroll
        for (int i = 0; i < 8; i++) {
            float e = Es[w * 8 + i][d];          // warp-uniform broadcast
            acc[i][0] += e * w2.x;
            acc[i][1] += e * w2.y;
        }
    }
#pragma unroll
    for (int i = 0; i < 8; i++) {
        int gr = n0 + w * 8 + i;
        if (gr < N_ENT) {
            size_t off = ((size_t)r * N_ENT + gr) * 64 + lane * 2;
            *(float2*)&g_proj[off] = make_float2(acc[i][0], acc[i][1]);
        }
    }
}

// ---------------- per-edge attention score + segment max ----------------
__global__ void k_att(const float* __restrict__ rel_emb,
                      const int* __restrict__ src,
                      const int* __restrict__ dst,
                      const int* __restrict__ et) {
    int e = blockIdx.x * 8 + (threadIdx.x >> 5);
    if (e >= N_EDGES) return;
    int lane = threadIdx.x & 31;
    int s = src[e], d = dst[e], r = et[e];

    const float* tp = g_proj + ((size_t)r * N_ENT + s) * 64;
    const float* hp = g_proj + ((size_t)r * N_ENT + d) * 64;
    const float* rp = rel_emb + r * 64;

    float2 t2 = *(const float2*)&tp[lane * 2];
    float2 h2 = *(const float2*)&hp[lane * 2];
    float2 r2 = *(const float2*)&rp[lane * 2];

    float v = t2.x * ftanh(h2.x + r2.x) + t2.y * ftanh(h2.y + r2.y);
#pragma unroll
    for (int o = 16; o; o >>= 1) v += __shfl_xor_sync(0xFFFFFFFFu, v, o);
    if (lane == 0) {
        g_att[e] = v;
        atomicMax(&g_mx[d], fkey(v));
    }
}

// ---------------- exp(att - mx[dst]) + segment sum ----------------
__global__ void k_exp(const int* __restrict__ dst) {
    int e = blockIdx.x * blockDim.x + threadIdx.x;
    if (e >= N_EDGES) return;
    int d = dst[e];
    float m = fdecode(g_mx[d]);
    float ev = __expf(g_att[e] - m);
    g_att[e] = ev;
    atomicAdd(&g_denom[d], ev);
}

// ---------------- normalize: w[e] = e[e] / denom[dst[e]] ----------------
__global__ void k_norm(const int* __restrict__ dst) {
    int e = blockIdx.x * blockDim.x + threadIdx.x;
    if (e >= N_EDGES) return;
    g_att[e] = __fdividef(g_att[e], g_denom[dst[e]]);
}

// ---------------- agg[dst] += h[src] * w  (warp per edge, RED.ADD) ----------------
__global__ void k_agg(const float* __restrict__ hsrc,
                      const int* __restrict__ src,
                      const int* __restrict__ dst,
                      int layer) {
    int e = blockIdx.x * 8 + (threadIdx.x >> 5);
    if (e >= N_EDGES) return;
    int lane = threadIdx.x & 31;
    int s = src[e], d = dst[e];
    const float* h = layer ? g_h1 : hsrc;
    float*     agg = layer ? g_agg2 : g_agg1;
    float w = g_att[e];
    float2 hv = *(const float2*)&h[(size_t)s * 64 + lane * 2];
    atomicAdd(&agg[(size_t)d * 64 + lane * 2],     hv.x * w);
    atomicAdd(&agg[(size_t)d * 64 + lane * 2 + 1], hv.y * w);
}

// ---------------- layer 1: h1 = lrelu((h0*agg1)@W0); out[:,0:64]=h0, out[:,64:128]=l2norm(h1) ----------------
__global__ void k_layer1(const float* __restrict__ ent,
                         const float* __restrict__ W0,
                         float* __restrict__ out) {
    __shared__ float Ws[64][64];
    __shared__ float xs[8][64];
    const int tid = threadIdx.x;
#pragma unroll
    for (int k = 0; k < 4; k++) {
        int idx = tid + k * 256;
        int row = idx >> 4, c4 = (idx & 15) * 4;
        *(float4*)&Ws[row][c4] = *(const float4*)&W0[row * 64 + c4];
    }
    __syncthreads();

    const int w = tid >> 5, lane = tid & 31;
    int n = blockIdx.x * 8 + w;
    if (n >= N_ENT) return;

    float2 h2 = *(const float2*)&ent[(size_t)n * 64 + lane * 2];
    float2 a2 = *(const float2*)&g_agg1[(size_t)n * 64 + lane * 2];
    xs[w][lane * 2]     = h2.x * a2.x;
    xs[w][lane * 2 + 1] = h2.y * a2.y;
    __syncwarp();

    float acc0 = 0.f, acc1 = 0.f;
#pragma unroll 8
    for (int d = 0; d < 64; d++) {
        float xd = xs[w][d];
        acc0 += xd * Ws[d][lane];
        acc1 += xd * Ws[d][lane + 32];
    }
    float v0 = (acc0 > 0.f) ? acc0 : 0.01f * acc0;
    float v1 = (acc1 > 0.f) ? acc1 : 0.01f * acc1;
    g_h1[(size_t)n * 64 + lane]      = v0;
    g_h1[(size_t)n * 64 + lane + 32] = v1;

    float sq = v0 * v0 + v1 * v1;
#pragma unroll
    for (int o = 16; o; o >>= 1) sq += __shfl_xor_sync(0xFFFFFFFFu, sq, o);
    float inv = 1.0f / fmaxf(sqrtf(sq), 1e-12f);

    float* orow = out + (size_t)n * 160;
    orow[2 * lane]     = h2.x;          // cache[0] = raw entity embed
    orow[2 * lane + 1] = h2.y;
    orow[64 + lane]      = v0 * inv;    // cache[1] = l2norm(h1)
    orow[64 + lane + 32] = v1 * inv;
}

// ---------------- layer 2: h2 = lrelu((h1*agg2)@W1); out[:,128:160]=l2norm(h2) ----------------
__global__ void k_layer2(const float* __restrict__ W1, float* __restrict__ out) {
    __shared__ float Ws[64][32];
    __shared__ float xs[8][64];
    const int tid = threadIdx.x;
#pragma unroll
    for (int k = 0; k < 2; k++) {
        int idx = tid + k * 256;
        int row = idx >> 3, c4 = (idx & 7) * 4;
        *(float4*)&Ws[row][c4] = *(const float4*)&W1[row * 32 + c4];
    }
    __syncthreads();

    const int w = tid >> 5, lane = tid & 31;
    int n = blockIdx.x * 8 + w;
    if (n >= N_ENT) return;

    float2 h2 = *(const float2*)&g_h1[(size_t)n * 64 + lane * 2];
    float2 a2 = *(const float2*)&g_agg2[(size_t)n * 64 + lane * 2];
    xs[w][lane * 2]     = h2.x * a2.x;
    xs[w][lane * 2 + 1] = h2.y * a2.y;
    __syncwarp();

    float acc = 0.f;
#pragma unroll 8
    for (int d = 0; d < 64; d++)
        acc += xs[w][d] * Ws[d][lane];

    float v = (acc > 0.f) ? acc : 0.01f * acc;
    float sq = v * v;
#pragma unroll
    for (int o = 16; o; o >>= 1) sq += __shfl_xor_sync(0xFFFFFFFFu, sq, o);
    float inv = 1.0f / fmaxf(sqrtf(sq), 1e-12f);
    out[(size_t)n * 160 + 128 + lane] = v * inv;
}

extern "C" void kernel_launch(void* const* d_in, const int* in_sizes, int n_in,
                              void* d_out, int out_size) {
    const float* ent = (const float*)d_in[0];
    const float* rel = (const float*)d_in[1];
    const float* WR  = (const float*)d_in[2];
    const float* W0  = (const float*)d_in[3];
    const float* W1  = (const float*)d_in[4];
    const int*   src = (const int*)d_in[5];   // JAX default x64=off -> int32
    const int*   dst = (const int*)d_in[6];
    const int*   et  = (const int*)d_in[7];
    float* out = (float*)d_out;

    (void)in_sizes; (void)n_in; (void)out_size;

    k_init<<<(N_ENT * DIM + 255) / 256, 256>>>();

    dim3 gp((N_ENT + 63) / 64, N_REL);
    k_proj<<<gp, 256>>>(ent, WR);

    const int geb = (N_EDGES + 7) / 8;           // warp per edge, 8 warps/block
    const int get = (N_EDGES + 255) / 256;       // thread per edge
    k_att<<<geb, 256>>>(rel, src, dst, et);
    k_exp<<<get, 256>>>(dst);
    k_norm<<<get, 256>>>(dst);

    const int gnb = (N_ENT + 7) / 8;             // warp per node
    k_agg<<<geb, 256>>>(ent, src, dst, /*layer=*/0);
    k_layer1<<<gnb, 256>>>(ent, W0, out);
    k_agg<<<geb, 256>>>(ent, src, dst, /*layer=*/1);
    k_layer2<<<gnb, 256>>>(W1, out);
}

// round 9
// speedup vs baseline: 1.3200x; 1.3200x over previous
#include <cuda_runtime.h>
#include <cuda_fp16.h>

#define N_ENT   100000
#define N_REL   16
#define DIM     64
#define N_EDGES 1600000

typedef unsigned long long ull;

// ---------------- device scratch (no allocs allowed) ----------------
__device__ __half g_proj[(size_t)N_REL * N_ENT * DIM];  // 204.8 MB, fp16
__device__ float g_att[N_EDGES];                        // att -> exp -> normalized w
__device__ int   g_mx[N_ENT];                           // float-ordered int keys
__device__ float g_denom[N_ENT];
__device__ float g_agg1[N_ENT * DIM];
__device__ float g_agg2[N_ENT * DIM];
__device__ float g_h1[N_ENT * DIM];                     // unnormalized layer-1 h

// ---------------- helpers ----------------
__device__ __forceinline__ int fkey(float f) {
    int i = __float_as_int(f);
    return (i >= 0) ? i : (i ^ 0x7FFFFFFF);
}
__device__ __forceinline__ float fdecode(int k) {
    return __int_as_float((k >= 0) ? k : (k ^ 0x7FFFFFFF));
}
__device__ __forceinline__ float ftanh(float x) {       // precise-enough tanh (MUFU.EX2 + RCP)
    x = fminf(fmaxf(x, -15.f), 15.f);
    float e = __expf(2.f * x);
    return __fdividef(e - 1.f, e + 1.f);
}
__device__ __forceinline__ ull pack2(float lo, float hi) {
    ull r; asm("mov.b64 %0, {%1, %2};" : "=l"(r) : "f"(lo), "f"(hi)); return r;
}
__device__ __forceinline__ float2 unpack2(ull v) {
    float lo, hi; asm("mov.b64 {%0, %1}, %2;" : "=f"(lo), "=f"(hi) : "l"(v));
    return make_float2(lo, hi);
}
// packed dual FMA: only reachable via PTX fma.rn.f32x2 (SASS FFMA2)
__device__ __forceinline__ ull ffma2(ull a, ull b, ull c) {
    ull d; asm("fma.rn.f32x2 %0, %1, %2, %3;" : "=l"(d) : "l"(a), "l"(b), "l"(c)); return d;
}

// ---------------- init: zero accumulators, reset softmax state ----------------
__global__ void k_init() {
    int idx = blockIdx.x * blockDim.x + threadIdx.x;
    if (idx < N_ENT * DIM) {
        g_agg1[idx] = 0.f;
        g_agg2[idx] = 0.f;
        if (idx < N_ENT) {
            g_mx[idx] = (int)0x80000000;
            g_denom[idx] = 0.f;
        }
    }
}

// ---------------- proj[r,n,:] = ent[n,:] @ W_R[r], stored fp16 ----------------
// block = 128 thr, tile = 64 nodes x 64 cols for one relation.
// thread owns 4 rows (rgrp*4..) x 8 cols (cgrp*8..); FFMA2 packs col pairs.
__global__ void __launch_bounds__(128) k_proj(const float* __restrict__ ent,
                                              const float* __restrict__ WR) {
    __shared__ float Es_t[64][68];   // transposed entity tile [d][row], padded
    __shared__ float Ws[64][64];     // W_R[r] [d][col]
    const int r  = blockIdx.y;
    const int n0 = blockIdx.x * 64;
    const int t  = threadIdx.x;

    const float* Wr = WR + (size_t)r * 4096;
#pragma unroll
    for (int k = 0; k < 8; k++) {
        int q   = t + k * 128;            // float4 slot 0..1023
        int row = q >> 4;
        int c4  = (q & 15) * 4;
        *(float4*)&Ws[row][c4] = *(const float4*)&Wr[row * 64 + c4];
        int gr = n0 + row;
        float4 e4 = make_float4(0.f, 0.f, 0.f, 0.f);
        if (gr < N_ENT) e4 = *(const float4*)&ent[(size_t)gr * 64 + c4];
        Es_t[c4 + 0][row] = e4.x;
        Es_t[c4 + 1][row] = e4.y;
        Es_t[c4 + 2][row] = e4.z;
        Es_t[c4 + 3][row] = e4.w;
    }
    __syncthreads();

    const int rgrp = t & 15;             // rows rgrp*4 .. +4
    const int cgrp = t >> 4;             // cols cgrp*8 .. +8

    ull acc[4][4];                       // [row][col-pair], each = {c,c+1}
#pragma unroll
    for (int i = 0; i < 4; i++)
#pragma unroll
        for (int j = 0; j < 4; j++) acc[i][j] = pack2(0.f, 0.f);

#pragma unroll 8
    for (int d = 0; d < 64; d++) {
        float4 ev = *(const float4*)&Es_t[d][rgrp * 4];
        ull e0 = pack2(ev.x, ev.x);
        ull e1 = pack2(ev.y, ev.y);
        ull e2 = pack2(ev.z, ev.z);
        ull e3 = pack2(ev.w, ev.w);
        const ull* wrow = (const ull*)&Ws[d][cgrp * 8];
        ull w0 = wrow[0], w1 = wrow[1], w2 = wrow[2], w3 = wrow[3];
        acc[0][0] = ffma2(e0, w0, acc[0][0]); acc[0][1] = ffma2(e0, w1, acc[0][1]);
        acc[0][2] = ffma2(e0, w2, acc[0][2]); acc[0][3] = ffma2(e0, w3, acc[0][3]);
        acc[1][0] = ffma2(e1, w0, acc[1][0]); acc[1][1] = ffma2(e1, w1, acc[1][1]);
        acc[1][2] = ffma2(e1, w2, acc[1][2]); acc[1][3] = ffma2(e1, w3, acc[1][3]);
        acc[2][0] = ffma2(e2, w0, acc[2][0]); acc[2][1] = ffma2(e2, w1, acc[2][1]);
        acc[2][2] = ffma2(e2, w2, acc[2][2]); acc[2][3] = ffma2(e2, w3, acc[2][3]);
        acc[3][0] = ffma2(e3, w0, acc[3][0]); acc[3][1] = ffma2(e3, w1, acc[3][1]);
        acc[3][2] = ffma2(e3, w2, acc[3][2]); acc[3][3] = ffma2(e3, w3, acc[3][3]);
    }

#pragma unroll
    for (int i = 0; i < 4; i++) {
        int gr = n0 + rgrp * 4 + i;
        if (gr < N_ENT) {
            __half2 o[4];
#pragma unroll
            for (int j = 0; j < 4; j++) {
                float2 f = unpack2(acc[i][j]);
                o[j] = __floats2half2_rn(f.x, f.y);
            }
            *(uint4*)&g_proj[((size_t)r * N_ENT + gr) * 64 + cgrp * 8] = *(uint4*)o;
        }
    }
}

// ---------------- per-edge attention score + segment max ----------------
// warp per edge: each fp16 proj row is exactly one 128B line.
__global__ void k_att(const float* __restrict__ rel_emb,
                      const int* __restrict__ src,
                      const int* __restrict__ dst,
                      const int* __restrict__ et) {
    int e = blockIdx.x * 8 + (threadIdx.x >> 5);
    if (e >= N_EDGES) return;
    int lane = threadIdx.x & 31;
    int s = src[e], d = dst[e], r = et[e];

    const __half2* gp = (const __half2*)g_proj;
    __half2 tph = gp[((size_t)r * N_ENT + s) * 32 + lane];
    __half2 hph = gp[((size_t)r * N_ENT + d) * 32 + lane];
    float2 t2 = __half22float2(tph);
    float2 h2 = __half22float2(hph);
    float2 r2 = *(const float2*)&rel_emb[r * 64 + lane * 2];

    float v = t2.x * ftanh(h2.x + r2.x) + t2.y * ftanh(h2.y + r2.y);
#pragma unroll
    for (int o = 16; o; o >>= 1) v += __shfl_xor_sync(0xFFFFFFFFu, v, o);
    if (lane == 0) {
        g_att[e] = v;
        atomicMax(&g_mx[d], fkey(v));
    }
}

// ---------------- exp(att - mx[dst]) + segment sum ----------------
__global__ void k_exp(const int* __restrict__ dst) {
    int e = blockIdx.x * blockDim.x + threadIdx.x;
    if (e >= N_EDGES) return;
    int d = dst[e];
    float m = fdecode(g_mx[d]);
    float ev = __expf(g_att[e] - m);
    g_att[e] = ev;
    atomicAdd(&g_denom[d], ev);
}

// ---------------- normalize: w[e] = e[e] / denom[dst[e]] ----------------
__global__ void k_norm(const int* __restrict__ dst) {
    int e = blockIdx.x * blockDim.x + threadIdx.x;
    if (e >= N_EDGES) return;
    g_att[e] = __fdividef(g_att[e], g_denom[dst[e]]);
}

// ---------------- agg[dst] += h[src] * w  (2 edges/warp, red.v4.f32) ----------------
__global__ void k_agg(const float* __restrict__ hsrc,
                      const int* __restrict__ src,
                      const int* __restrict__ dst,
                      int layer) {
    int e = blockIdx.x * 16 + (threadIdx.x >> 4);
    if (e >= N_EDGES) return;
    int l = threadIdx.x & 15;
    int s = src[e], d = dst[e];
    const float* h = layer ? g_h1 : hsrc;
    float*     agg = layer ? g_agg2 : g_agg1;
    float w = g_att[e];
    float4 hv = *(const float4*)&h[(size_t)s * 64 + l * 4];
    float* ap = &agg[(size_t)d * 64 + l * 4];
    asm volatile("red.global.add.v4.f32 [%0], {%1, %2, %3, %4};"
                 :: "l"(ap), "f"(hv.x * w), "f"(hv.y * w), "f"(hv.z * w), "f"(hv.w * w)
                 : "memory");
}

// ---------------- layer 1 ----------------
__global__ void k_layer1(const float* __restrict__ ent,
                         const float* __restrict__ W0,
                         float* __restrict__ out) {
    __shared__ float Ws[64][64];
    __shared__ float xs[8][64];
    const int tid = threadIdx.x;
#pragma unroll
    for (int k = 0; k < 4; k++) {
        int idx = tid + k * 256;
        int row = idx >> 4, c4 = (idx & 15) * 4;
        *(float4*)&Ws[row][c4] = *(const float4*)&W0[row * 64 + c4];
    }
    __syncthreads();

    const int w = tid >> 5, lane = tid & 31;
    int n = blockIdx.x * 8 + w;
    if (n >= N_ENT) return;

    float2 h2 = *(const float2*)&ent[(size_t)n * 64 + lane * 2];
    float2 a2 = *(const float2*)&g_agg1[(size_t)n * 64 + lane * 2];
    xs[w][lane * 2]     = h2.x * a2.x;
    xs[w][lane * 2 + 1] = h2.y * a2.y;
    __syncwarp();

    float acc0 = 0.f, acc1 = 0.f;
#pragma unroll 8
    for (int d = 0; d < 64; d++) {
        float xd = xs[w][d];
        acc0 += xd * Ws[d][lane];
        acc1 += xd * Ws[d][lane + 32];
    }
    float v0 = (acc0 > 0.f) ? acc0 : 0.01f * acc0;
    float v1 = (acc1 > 0.f) ? acc1 : 0.01f * acc1;
    g_h1[(size_t)n * 64 + lane]      = v0;
    g_h1[(size_t)n * 64 + lane + 32] = v1;

    float sq = v0 * v0 + v1 * v1;
#pragma unroll
    for (int o = 16; o; o >>= 1) sq += __shfl_xor_sync(0xFFFFFFFFu, sq, o);
    float inv = 1.0f / fmaxf(sqrtf(sq), 1e-12f);

    float* orow = out + (size_t)n * 160;
    orow[2 * lane]     = h2.x;
    orow[2 * lane + 1] = h2.y;
    orow[64 + lane]      = v0 * inv;
    orow[64 + lane + 32] = v1 * inv;
}

// ---------------- layer 2 ----------------
__global__ void k_layer2(const float* __restrict__ W1, float* __restrict__ out) {
    __shared__ float Ws[64][32];
    __shared__ float xs[8][64];
    const int tid = threadIdx.x;
#pragma unroll
    for (int k = 0; k < 2; k++) {
        int idx = tid + k * 256;
        int row = idx >> 3, c4 = (idx & 7) * 4;
        *(float4*)&Ws[row][c4] = *(const float4*)&W1[row * 32 + c4];
    }
    __syncthreads();

    const int w = tid >> 5, lane = tid & 31;
    int n = blockIdx.x * 8 + w;
    if (n >= N_ENT) return;

    float2 h2 = *(const float2*)&g_h1[(size_t)n * 64 + lane * 2];
    float2 a2 = *(const float2*)&g_agg2[(size_t)n * 64 + lane * 2];
    xs[w][lane * 2]     = h2.x * a2.x;
    xs[w][lane * 2 + 1] = h2.y * a2.y;
    __syncwarp();

    float acc = 0.f;
#pragma unroll 8
    for (int d = 0; d < 64; d++)
        acc += xs[w][d] * Ws[d][lane];

    float v = (acc > 0.f) ? acc : 0.01f * acc;
    float sq = v * v;
#pragma unroll
    for (int o = 16; o; o >>= 1) sq += __shfl_xor_sync(0xFFFFFFFFu, sq, o);
    float inv = 1.0f / fmaxf(sqrtf(sq), 1e-12f);
    out[(size_t)n * 160 + 128 + lane] = v * inv;
}

extern "C" void kernel_launch(void* const* d_in, const int* in_sizes, int n_in,
                              void* d_out, int out_size) {
    const float* ent = (const float*)d_in[0];
    const float* rel = (const float*)d_in[1];
    const float* WR  = (const float*)d_in[2];
    const float* W0  = (const float*)d_in[3];
    const float* W1  = (const float*)d_in[4];
    const int*   src = (const int*)d_in[5];   // JAX x64 off -> int32
    const int*   dst = (const int*)d_in[6];
    const int*   et  = (const int*)d_in[7];
    float* out = (float*)d_out;

    (void)in_sizes; (void)n_in; (void)out_size;

    k_init<<<(N_ENT * DIM + 255) / 256, 256>>>();

    dim3 gp((N_ENT + 63) / 64, N_REL);
    k_proj<<<gp, 128>>>(ent, WR);

    const int geb  = (N_EDGES + 7) / 8;          // warp per edge
    const int geb2 = (N_EDGES + 15) / 16;        // 2 edges per warp
    const int get  = (N_EDGES + 255) / 256;      // thread per edge
    k_att<<<geb, 256>>>(rel, src, dst, et);
    k_exp<<<get, 256>>>(dst);
    k_norm<<<get, 256>>>(dst);

    const int gnb = (N_ENT + 7) / 8;             // warp per node
    k_agg<<<geb2, 256>>>(ent, src, dst, /*layer=*/0);
    k_layer1<<<gnb, 256>>>(ent, W0, out);
    k_agg<<<geb2, 256>>>(ent, src, dst, /*layer=*/1);
    k_layer2<<<gnb, 256>>>(W1, out);
}